// round 9
// baseline (speedup 1.0000x reference)
#include <cuda_runtime.h>
#include <cuda_bf16.h>
#include <cstdint>
#include <cstddef>

#define BATCH 8
#define SEQ   1024
#define CDIM  768
#define HEADS 12
#define MTOK  (BATCH*SEQ)      // 8192
#define QKVC  (3*CDIM)         // 2304
#define NSEQ2 ((size_t)BATCH * HEADS * SEQ * SEQ)

// Persistent scratch (device globals — allocation is forbidden)
__device__ __nv_bfloat16 g_x_hi   [(size_t)MTOK * CDIM];
__device__ __nv_bfloat16 g_x_mid  [(size_t)MTOK * CDIM];
__device__ __nv_bfloat16 g_wqkv_hi [(size_t)QKVC * CDIM];
__device__ __nv_bfloat16 g_wqkv_mid[(size_t)QKVC * CDIM];
__device__ __nv_bfloat16 g_wproj_hi [(size_t)CDIM * CDIM];
__device__ __nv_bfloat16 g_wproj_mid[(size_t)CDIM * CDIM];
__device__ __nv_bfloat16 g_qkv_hi [(size_t)MTOK * QKVC];
__device__ __nv_bfloat16 g_qkv_mid[(size_t)MTOK * QKVC];
__device__ __nv_bfloat16 g_ctx_hi [(size_t)MTOK * CDIM];
__device__ __nv_bfloat16 g_ctx_mid[(size_t)MTOK * CDIM];
__device__ __nv_bfloat16 g_e_hi [NSEQ2];    // exp(S) hi plane
__device__ __nv_bfloat16 g_e_mid[NSEQ2];    // exp(S) mid plane
__device__ float g_rowsum[(size_t)BATCH * HEADS * SEQ];

// ---------------------------------------------------------------------------
__device__ __forceinline__ void mma16816(float* d, const uint32_t* a, const uint32_t* b)
{
    asm volatile(
        "mma.sync.aligned.m16n8k16.row.col.f32.bf16.bf16.f32 "
        "{%0,%1,%2,%3},{%4,%5,%6,%7},{%8,%9},{%0,%1,%2,%3};\n"
        : "+f"(d[0]), "+f"(d[1]), "+f"(d[2]), "+f"(d[3])
        : "r"(a[0]), "r"(a[1]), "r"(a[2]), "r"(a[3]), "r"(b[0]), "r"(b[1]));
}

__device__ __forceinline__ void ldsm_x4(uint32_t* r, uint32_t saddr)
{
    asm volatile("ldmatrix.sync.aligned.m8n8.x4.shared.b16 {%0,%1,%2,%3}, [%4];"
        : "=r"(r[0]), "=r"(r[1]), "=r"(r[2]), "=r"(r[3]) : "r"(saddr));
}

__device__ __forceinline__ void ldsm_x4_t(uint32_t* r, uint32_t saddr)
{
    asm volatile("ldmatrix.sync.aligned.m8n8.x4.trans.shared.b16 {%0,%1,%2,%3}, [%4];"
        : "=r"(r[0]), "=r"(r[1]), "=r"(r[2]), "=r"(r[3]) : "r"(saddr));
}

__device__ __forceinline__ void cp_async16(uint32_t saddr, const void* gptr)
{
    asm volatile("cp.async.cg.shared.global [%0], [%1], 16;"
        :: "r"(saddr), "l"(gptr));
}
#define CP_COMMIT() asm volatile("cp.async.commit_group;" ::: "memory")
#define CP_WAIT0()  asm volatile("cp.async.wait_group 0;" ::: "memory")

__device__ __forceinline__ void cvt_pair(float x, float y, uint32_t& hi, uint32_t& mid)
{
    __nv_bfloat162 h = __floats2bfloat162_rn(x, y);
    float rx = x - __bfloat162float(__low2bfloat16(h));
    float ry = y - __bfloat162float(__high2bfloat16(h));
    __nv_bfloat162 m = __floats2bfloat162_rn(rx, ry);
    hi  = *reinterpret_cast<uint32_t*>(&h);
    mid = *reinterpret_cast<uint32_t*>(&m);
}

// ---------------------------------------------------------------------------
// Fused prep: split x/wqkv/wproj into hi/mid planes + zero rowsums. One launch.
// ---------------------------------------------------------------------------
#define N4_X   (MTOK * CDIM / 4)
#define N4_WQ  (QKVC * CDIM / 4)
#define N4_WP  (CDIM * CDIM / 4)
#define N4_RS  (BATCH * HEADS * SEQ / 4)

__global__ __launch_bounds__(256) void prep_kernel(
    const float* __restrict__ x, const float* __restrict__ wq,
    const float* __restrict__ wp,
    __nv_bfloat16* __restrict__ x_hi, __nv_bfloat16* __restrict__ x_mid,
    __nv_bfloat16* __restrict__ wq_hi, __nv_bfloat16* __restrict__ wq_mid,
    __nv_bfloat16* __restrict__ wp_hi, __nv_bfloat16* __restrict__ wp_mid,
    float* __restrict__ rs)
{
    int i = blockIdx.x * blockDim.x + threadIdx.x;
    const float* src; __nv_bfloat16 *hi, *mid; int off;
    if (i < N4_X)                        { src = x;  hi = x_hi;  mid = x_mid;  off = 0; }
    else if (i < N4_X + N4_WQ)           { src = wq; hi = wq_hi; mid = wq_mid; off = N4_X; }
    else if (i < N4_X + N4_WQ + N4_WP)   { src = wp; hi = wp_hi; mid = wp_mid; off = N4_X + N4_WQ; }
    else if (i < N4_X + N4_WQ + N4_WP + N4_RS) {
        ((float4*)rs)[i - (N4_X + N4_WQ + N4_WP)] = make_float4(0.f, 0.f, 0.f, 0.f);
        return;
    } else return;
    int j = i - off;
    float4 v = ((const float4*)src)[j];
    uint32_t h0, m0, h1, m1;
    cvt_pair(v.x, v.y, h0, m0);
    cvt_pair(v.z, v.w, h1, m1);
    ((uint2*)hi)[j]  = make_uint2(h0, h1);
    ((uint2*)mid)[j] = make_uint2(m0, m1);
}

// ---------------------------------------------------------------------------
// Batched GEMM on pre-split bf16 hi/mid operands. 3 MMAs (hh, hm, mh).
// ASRC=0: A via cp.async from (Ahi,Amid).
// ASRC=2: same staging + per-tile P-write: p=(hi+mid)*inv from smem -> Af32,
//         and epilogue scales acc by 1/rowsum (PV kernel).
// BTRANS=0: B [N,K] k-contig (ldmatrix). BTRANS=1: B [K,N] n-contig (ldmatrix.trans).
// OUT=0: C fp32 + bias.  OUT=2: C -> hi/mid planes.
// OUT=3: exp(alpha*acc) -> hi/mid planes + rowsum atomics (S kernel).
// ---------------------------------------------------------------------------
template<int BM, int BN, int WM, int WN, int ASRC, int BTRANS, int OUT>
__global__ __launch_bounds__(256, 2) void gemm3(
    const __nv_bfloat16* __restrict__ Ahi, const __nv_bfloat16* __restrict__ Amid,
    float* __restrict__ Af32, int lda, long long sa1, long long sa2,
    const __nv_bfloat16* __restrict__ Bhi, const __nv_bfloat16* __restrict__ Bmid,
    int ldb, long long sb1, long long sb2,
    float* __restrict__ Cf, __nv_bfloat16* __restrict__ Chi, __nv_bfloat16* __restrict__ Cmid,
    int ldc, long long sc1, long long sc2,
    int K, int nz2, float alpha, const float* __restrict__ bias,
    float* __restrict__ rowsum)
{
    constexpr int BK  = 32;
    constexpr int BKP = 40;       // A / B(k-contig) row stride, 80B = 16B-aligned
    constexpr int BNP = 72;       // B(trans) row stride, 144B = 16B-aligned
    constexpr int MW  = BM / WM;
    constexpr int MF  = WM / 16;
    constexpr int NF  = WN / 8;

    extern __shared__ __nv_bfloat16 sm[];
    __nv_bfloat16* Asm = sm;                         // [2][2][BM][BKP]
    __nv_bfloat16* Bsm = sm + 4 * BM * BKP;
#define ASM(bb,s,m,k)  Asm[(((bb)*2+(s))*BM + (m))*BKP + (k)]
#define BSM(bb,s,n,k)  Bsm[(((bb)*2+(s))*BN + (n))*BKP + (k)]
#define BSMT(bb,s,k,n) Bsm[(((bb)*2+(s))*BK + (k))*BNP + (n)]
    const uint32_t asm_u32 = (uint32_t)__cvta_generic_to_shared(Asm);
    const uint32_t bsm_u32 = (uint32_t)__cvta_generic_to_shared(Bsm);

    const int z  = blockIdx.z;
    const int z1 = z / nz2, z2 = z - z1 * nz2;
    const long long zofA = z1 * sa1 + z2 * sa2;
    const long long zofB = z1 * sb1 + z2 * sb2;
    const long long zofC = z1 * sc1 + z2 * sc2;

    const int m0  = blockIdx.y * BM;
    const int n0  = blockIdx.x * BN;
    const int tid = threadIdx.x;
    const int w    = tid >> 5, lane = tid & 31;
    const int wm   = w % MW,   wn   = w / MW;
    const int g    = lane >> 2;
    const int t2   = (lane & 3) * 2;

    // ldmatrix lane offsets (proven mappings — do not touch)
    const int a_row_off = ((lane >> 3) & 1) * 8 + (lane & 7);
    const int a_col_off = (lane >> 4) * 8;
    const int b_row_off = (lane >> 4) * 8 + (lane & 7);
    const int b_col_off = ((lane >> 3) & 1) * 8;
    const int bt_k_off = ((lane >> 3) & 1) * 8 + (lane & 7);
    const int bt_n_off = (lane >> 4) * 8;

    float acc[MF][NF][4];
#pragma unroll
    for (int i = 0; i < MF; i++)
#pragma unroll
        for (int j = 0; j < NF; j++)
#pragma unroll
            for (int q = 0; q < 4; q++) acc[i][j][q] = 0.0f;

    // ---- staging indices ----
    const int a_row = tid >> 1;            // 0..127
    const int a_seg = (tid & 1) * 16;
    const int bt_k  = tid >> 3;            // 0..31
    const int bt_sg = (tid & 7) * 8;

    float anorm = 1.0f;
    if (ASRC == 2)
        anorm = 1.0f / rowsum[(size_t)z * SEQ + m0 + a_row];

    // issue all async copies for k-tile kt into buffer bb
    auto issue_tile = [&](int kt, int bb) {
        {
            const __nv_bfloat16* ph = Ahi + zofA + (size_t)(m0 + a_row) * lda + kt + a_seg;
            const __nv_bfloat16* pm = Amid + zofA + (size_t)(m0 + a_row) * lda + kt + a_seg;
            uint32_t d0 = asm_u32 + (uint32_t)((((bb * 2 + 0) * BM + a_row) * BKP + a_seg) * 2);
            uint32_t d1 = asm_u32 + (uint32_t)((((bb * 2 + 1) * BM + a_row) * BKP + a_seg) * 2);
            cp_async16(d0,      ph);
            cp_async16(d0 + 16, ph + 8);
            cp_async16(d1,      pm);
            cp_async16(d1 + 16, pm + 8);
        }
        if (BTRANS == 0) {
            const __nv_bfloat16* ph = Bhi + zofB + (size_t)(n0 + a_row) * ldb + kt + a_seg;
            const __nv_bfloat16* pm = Bmid + zofB + (size_t)(n0 + a_row) * ldb + kt + a_seg;
            uint32_t d0 = bsm_u32 + (uint32_t)((((bb * 2 + 0) * BN + a_row) * BKP + a_seg) * 2);
            uint32_t d1 = bsm_u32 + (uint32_t)((((bb * 2 + 1) * BN + a_row) * BKP + a_seg) * 2);
            cp_async16(d0,      ph);
            cp_async16(d0 + 16, ph + 8);
            cp_async16(d1,      pm);
            cp_async16(d1 + 16, pm + 8);
        } else {
            const __nv_bfloat16* ph = Bhi + zofB + (size_t)(kt + bt_k) * ldb + n0 + bt_sg;
            const __nv_bfloat16* pm = Bmid + zofB + (size_t)(kt + bt_k) * ldb + n0 + bt_sg;
            uint32_t d0 = bsm_u32 + (uint32_t)((((bb * 2 + 0) * BK + bt_k) * BNP + bt_sg) * 2);
            uint32_t d1 = bsm_u32 + (uint32_t)((((bb * 2 + 1) * BK + bt_k) * BNP + bt_sg) * 2);
            cp_async16(d0, ph);
            cp_async16(d1, pm);
        }
    };

    // ASRC=2: reconstruct P = (hi+mid)*inv from staged smem, write fp32 attn
    auto pwrite = [&](int kt, int bb) {
        if (ASRC != 2) return;
        uint4 h0 = *(const uint4*)&ASM(bb, 0, a_row, a_seg);
        uint4 h1 = *(const uint4*)&ASM(bb, 0, a_row, a_seg + 8);
        uint4 mm0 = *(const uint4*)&ASM(bb, 1, a_row, a_seg);
        uint4 mm1 = *(const uint4*)&ASM(bb, 1, a_row, a_seg + 8);
        float* dst = Af32 + zofA + (size_t)(m0 + a_row) * lda + kt + a_seg;
        const uint32_t* hw = (const uint32_t*)&h0;   // h0,h1 contiguous? no — handle separately
        float4 o;
        const uint32_t ha[8] = { h0.x, h0.y, h0.z, h0.w, h1.x, h1.y, h1.z, h1.w };
        const uint32_t ma[8] = { mm0.x, mm0.y, mm0.z, mm0.w, mm1.x, mm1.y, mm1.z, mm1.w };
        (void)hw;
#pragma unroll
        for (int q = 0; q < 4; q++) {
            __nv_bfloat162 hx = *reinterpret_cast<const __nv_bfloat162*>(&ha[q * 2]);
            __nv_bfloat162 hy = *reinterpret_cast<const __nv_bfloat162*>(&ha[q * 2 + 1]);
            __nv_bfloat162 mx = *reinterpret_cast<const __nv_bfloat162*>(&ma[q * 2]);
            __nv_bfloat162 my = *reinterpret_cast<const __nv_bfloat162*>(&ma[q * 2 + 1]);
            o.x = (__low2float(hx)  + __low2float(mx))  * anorm;
            o.y = (__high2float(hx) + __high2float(mx)) * anorm;
            o.z = (__low2float(hy)  + __low2float(my))  * anorm;
            o.w = (__high2float(hy) + __high2float(my)) * anorm;
            *(float4*)(dst + 4 * q) = o;
        }
    };

    const int iters = K / BK;

    issue_tile(0, 0);
    CP_COMMIT();
    CP_WAIT0();
    __syncthreads();
    pwrite(0, 0);

    for (int it = 0; it < iters; it++) {
        const int buf = it & 1;
        const bool more = (it + 1 < iters);
        if (more) {
            issue_tile((it + 1) * BK, buf ^ 1);   // overlaps with compute below
            CP_COMMIT();
        }

#pragma unroll
        for (int ks = 0; ks < BK; ks += 16) {
            uint32_t af[2][MF][4], bf[2][NF][2];
#pragma unroll
            for (int s = 0; s < 2; s++) {
#pragma unroll
                for (int i = 0; i < MF; i++) {
                    int row = wm * WM + i * 16 + a_row_off;
                    int col = ks + a_col_off;
                    uint32_t addr = asm_u32 +
                        (uint32_t)((((buf * 2 + s) * BM + row) * BKP + col) * 2);
                    ldsm_x4(af[s][i], addr);
                }
#pragma unroll
                for (int jj = 0; jj < NF / 2; jj++) {
                    uint32_t r[4];
                    if (BTRANS == 0) {
                        int row = wn * WN + jj * 16 + b_row_off;
                        int col = ks + b_col_off;
                        uint32_t addr = bsm_u32 +
                            (uint32_t)((((buf * 2 + s) * BN + row) * BKP + col) * 2);
                        ldsm_x4(r, addr);
                    } else {
                        int kR = ks + bt_k_off;
                        int nB = wn * WN + jj * 16 + bt_n_off;
                        uint32_t addr = bsm_u32 +
                            (uint32_t)((((buf * 2 + s) * BK + kR) * BNP + nB) * 2);
                        ldsm_x4_t(r, addr);
                    }
                    bf[s][jj * 2 + 0][0] = r[0]; bf[s][jj * 2 + 0][1] = r[1];
                    bf[s][jj * 2 + 1][0] = r[2]; bf[s][jj * 2 + 1][1] = r[3];
                }
            }
#pragma unroll
            for (int i = 0; i < MF; i++)
#pragma unroll
                for (int j = 0; j < NF; j++) {
                    mma16816(acc[i][j], af[0][i], bf[0][j]);   // hi*hi
                    mma16816(acc[i][j], af[0][i], bf[1][j]);   // hi*mid
                    mma16816(acc[i][j], af[1][i], bf[0][j]);   // mid*hi
                }
        }

        if (more) CP_WAIT0();
        __syncthreads();
        if (more) pwrite((it + 1) * BK, buf ^ 1);
    }

    // ---- epilogue ----
    if (OUT == 3) {
        // exp -> hi/mid planes + rowsum atomics (S kernel)
        __nv_bfloat16* Ch = Chi + zofC;
        __nv_bfloat16* Cm = Cmid + zofC;
        float rs[MF][2];
#pragma unroll
        for (int i = 0; i < MF; i++) { rs[i][0] = 0.0f; rs[i][1] = 0.0f; }
#pragma unroll
        for (int i = 0; i < MF; i++) {
            int r = m0 + wm * WM + i * 16 + g;
#pragma unroll
            for (int j = 0; j < NF; j++) {
                int c = n0 + wn * WN + j * 8 + t2;
                float e0 = __expf(alpha * acc[i][j][0]);
                float e1 = __expf(alpha * acc[i][j][1]);
                float e2 = __expf(alpha * acc[i][j][2]);
                float e3 = __expf(alpha * acc[i][j][3]);
                uint32_t h, mmv;
                cvt_pair(e0, e1, h, mmv);
                *(uint32_t*)&Ch[(size_t)r * ldc + c] = h;
                *(uint32_t*)&Cm[(size_t)r * ldc + c] = mmv;
                cvt_pair(e2, e3, h, mmv);
                *(uint32_t*)&Ch[(size_t)(r + 8) * ldc + c] = h;
                *(uint32_t*)&Cm[(size_t)(r + 8) * ldc + c] = mmv;
                rs[i][0] += e0 + e1;
                rs[i][1] += e2 + e3;
            }
        }
#pragma unroll
        for (int i = 0; i < MF; i++) {
            rs[i][0] += __shfl_xor_sync(0xffffffffu, rs[i][0], 1);
            rs[i][0] += __shfl_xor_sync(0xffffffffu, rs[i][0], 2);
            rs[i][1] += __shfl_xor_sync(0xffffffffu, rs[i][1], 1);
            rs[i][1] += __shfl_xor_sync(0xffffffffu, rs[i][1], 2);
        }
        if ((lane & 3) == 0) {
            size_t base = (size_t)z * SEQ + m0 + wm * WM;
#pragma unroll
            for (int i = 0; i < MF; i++) {
                atomicAdd(&rowsum[base + i * 16 + g],     rs[i][0]);
                atomicAdd(&rowsum[base + i * 16 + 8 + g], rs[i][1]);
            }
        }
    } else if (OUT == 2) {
        __nv_bfloat16* Ch = Chi + zofC;
        __nv_bfloat16* Cm = Cmid + zofC;
#pragma unroll
        for (int i = 0; i < MF; i++) {
            int r = m0 + wm * WM + i * 16 + g;
            float inv0 = 1.0f, inv1 = 1.0f;
            if (ASRC == 2) {
                inv0 = 1.0f / rowsum[(size_t)z * SEQ + r];
                inv1 = 1.0f / rowsum[(size_t)z * SEQ + r + 8];
            }
#pragma unroll
            for (int j = 0; j < NF; j++) {
                int c = n0 + wn * WN + j * 8 + t2;
                uint32_t h, mmv;
                cvt_pair(acc[i][j][0] * inv0, acc[i][j][1] * inv0, h, mmv);
                *(uint32_t*)&Ch[(size_t)r * ldc + c] = h;
                *(uint32_t*)&Cm[(size_t)r * ldc + c] = mmv;
                cvt_pair(acc[i][j][2] * inv1, acc[i][j][3] * inv1, h, mmv);
                *(uint32_t*)&Ch[(size_t)(r + 8) * ldc + c] = h;
                *(uint32_t*)&Cm[(size_t)(r + 8) * ldc + c] = mmv;
            }
        }
    } else {
        float* C = Cf + zofC;
#pragma unroll
        for (int i = 0; i < MF; i++) {
            int r = m0 + wm * WM + i * 16 + g;
#pragma unroll
            for (int j = 0; j < NF; j++) {
                int c = n0 + wn * WN + j * 8 + t2;
                float b0 = bias ? bias[c]     : 0.0f;
                float b1 = bias ? bias[c + 1] : 0.0f;
                *(float2*)&C[(size_t)r * ldc + c] =
                    make_float2(acc[i][j][0] + b0, acc[i][j][1] + b1);
                *(float2*)&C[(size_t)(r + 8) * ldc + c] =
                    make_float2(acc[i][j][2] + b0, acc[i][j][3] + b1);
            }
        }
    }
#undef ASM
#undef BSM
#undef BSMT
}

// ---------------------------------------------------------------------------
extern "C" void kernel_launch(void* const* d_in, const int* in_sizes, int n_in,
                              void* d_out, int out_size)
{
    const float* x      = (const float*)d_in[0];   // [8,1024,768]
    const float* qkv_w  = (const float*)d_in[1];   // [2304,768]
    const float* proj_w = (const float*)d_in[2];   // [768,768]
    const float* proj_b = (const float*)d_in[3];   // [768]

    float* out_proj = (float*)d_out;                          // [8,1024,768]
    float* out_attn = (float*)d_out + (size_t)MTOK * CDIM;    // [8,12,1024,1024]

    __nv_bfloat16 *x_hi, *x_mid, *wq_hi, *wq_mid, *wp_hi, *wp_mid;
    __nv_bfloat16 *qkv_hi, *qkv_mid, *ctx_hi, *ctx_mid, *e_hi, *e_mid;
    float* rsum;
    cudaGetSymbolAddress((void**)&x_hi,   g_x_hi);
    cudaGetSymbolAddress((void**)&x_mid,  g_x_mid);
    cudaGetSymbolAddress((void**)&wq_hi,  g_wqkv_hi);
    cudaGetSymbolAddress((void**)&wq_mid, g_wqkv_mid);
    cudaGetSymbolAddress((void**)&wp_hi,  g_wproj_hi);
    cudaGetSymbolAddress((void**)&wp_mid, g_wproj_mid);
    cudaGetSymbolAddress((void**)&qkv_hi, g_qkv_hi);
    cudaGetSymbolAddress((void**)&qkv_mid,g_qkv_mid);
    cudaGetSymbolAddress((void**)&ctx_hi, g_ctx_hi);
    cudaGetSymbolAddress((void**)&ctx_mid,g_ctx_mid);
    cudaGetSymbolAddress((void**)&e_hi,   g_e_hi);
    cudaGetSymbolAddress((void**)&e_mid,  g_e_mid);
    cudaGetSymbolAddress((void**)&rsum,   g_rowsum);

    constexpr int BKP = 40, BNP = 72;
    constexpr int SM_KC = (4 * 128 * BKP + 4 * 128 * BKP) * 2;   // 81920 B
    constexpr int SM_TR = (4 * 128 * BKP + 4 * 32 * BNP) * 2;    // 59392 B

    cudaFuncSetAttribute((const void*)gemm3<128,128,64,32,0,0,2>,
                         cudaFuncAttributeMaxDynamicSharedMemorySize, SM_KC);
    cudaFuncSetAttribute((const void*)gemm3<128,128,64,32,0,0,3>,
                         cudaFuncAttributeMaxDynamicSharedMemorySize, SM_KC);
    cudaFuncSetAttribute((const void*)gemm3<128,64,32,32,2,1,2>,
                         cudaFuncAttributeMaxDynamicSharedMemorySize, SM_TR);
    cudaFuncSetAttribute((const void*)gemm3<128,128,64,32,0,0,0>,
                         cudaFuncAttributeMaxDynamicSharedMemorySize, SM_KC);

    // 0) fused prep: splits + rowsum zero (one launch)
    {
        int total = N4_X + N4_WQ + N4_WP + N4_RS;
        prep_kernel<<<(total + 255) / 256, 256>>>(
            x, qkv_w, proj_w, x_hi, x_mid, wq_hi, wq_mid, wp_hi, wp_mid, rsum);
    }

    // 1) QKV GEMM -> split planes g_qkv
    gemm3<128,128,64,32,0,0,2><<<dim3(QKVC/128, MTOK/128, 1), 256, SM_KC>>>(
        x_hi, x_mid, nullptr, CDIM, 0, 0,
        wq_hi, wq_mid, CDIM, 0, 0,
        nullptr, qkv_hi, qkv_mid, QKVC, 0, 0,
        CDIM, 1, 1.0f, nullptr, rsum);

    // 2) E = exp(0.125 * Q @ K^T) -> hi/mid planes + rowsums
    gemm3<128,128,64,32,0,0,3><<<dim3(SEQ/128, SEQ/128, BATCH*HEADS), 256, SM_KC>>>(
        qkv_hi, qkv_mid, nullptr, QKVC, (long long)SEQ * QKVC, 64,
        qkv_hi + CDIM, qkv_mid + CDIM, QKVC, (long long)SEQ * QKVC, 64,
        nullptr, e_hi, e_mid, SEQ,
        (long long)HEADS * SEQ * SEQ, (long long)SEQ * SEQ,
        64, HEADS, 0.125f, nullptr, rsum);

    // 3) ctx = (E @ V) * inv; writes P fp32 to out_attn from staged smem
    gemm3<128,64,32,32,2,1,2><<<dim3(1, SEQ/128, BATCH*HEADS), 256, SM_TR>>>(
        e_hi, e_mid, out_attn, SEQ,
        (long long)HEADS * SEQ * SEQ, (long long)SEQ * SEQ,
        qkv_hi + 2 * CDIM, qkv_mid + 2 * CDIM, QKVC, (long long)SEQ * QKVC, 64,
        nullptr, ctx_hi, ctx_mid, CDIM, (long long)SEQ * CDIM, 64,
        SEQ, HEADS, 1.0f, nullptr, rsum);

    // 4) proj: ctx @ proj_w^T + bias -> out (fp32)
    gemm3<128,128,64,32,0,0,0><<<dim3(CDIM/128, MTOK/128, 1), 256, SM_KC>>>(
        ctx_hi, ctx_mid, nullptr, CDIM, 0, 0,
        wp_hi, wp_mid, CDIM, 0, 0,
        out_proj, nullptr, nullptr, CDIM, 0, 0,
        CDIM, 1, 1.0f, proj_b, rsum);
}

// round 11
// speedup vs baseline: 1.1074x; 1.1074x over previous
#include <cuda_runtime.h>
#include <cuda_bf16.h>
#include <cstdint>
#include <cstddef>

#define BATCH 8
#define SEQ   1024
#define CDIM  768
#define HEADS 12
#define MTOK  (BATCH*SEQ)      // 8192
#define QKVC  (3*CDIM)         // 2304

// Persistent scratch (device globals — allocation is forbidden)
__device__ __nv_bfloat16 g_x_hi   [(size_t)MTOK * CDIM];
__device__ __nv_bfloat16 g_x_mid  [(size_t)MTOK * CDIM];
__device__ __nv_bfloat16 g_wqkv_hi [(size_t)QKVC * CDIM];
__device__ __nv_bfloat16 g_wqkv_mid[(size_t)QKVC * CDIM];
__device__ __nv_bfloat16 g_wproj_hi [(size_t)CDIM * CDIM];
__device__ __nv_bfloat16 g_wproj_mid[(size_t)CDIM * CDIM];
__device__ __nv_bfloat16 g_qkv_hi [(size_t)MTOK * QKVC];
__device__ __nv_bfloat16 g_qkv_mid[(size_t)MTOK * QKVC];
__device__ __nv_bfloat16 g_ctx_hi [(size_t)MTOK * CDIM];
__device__ __nv_bfloat16 g_ctx_mid[(size_t)MTOK * CDIM];
__device__ float g_rowsum[(size_t)BATCH * HEADS * SEQ];

// ---------------------------------------------------------------------------
__device__ __forceinline__ void mma16816(float* d, const uint32_t* a, const uint32_t* b)
{
    asm volatile(
        "mma.sync.aligned.m16n8k16.row.col.f32.bf16.bf16.f32 "
        "{%0,%1,%2,%3},{%4,%5,%6,%7},{%8,%9},{%0,%1,%2,%3};\n"
        : "+f"(d[0]), "+f"(d[1]), "+f"(d[2]), "+f"(d[3])
        : "r"(a[0]), "r"(a[1]), "r"(a[2]), "r"(a[3]), "r"(b[0]), "r"(b[1]));
}

__device__ __forceinline__ void ldsm_x4(uint32_t* r, uint32_t saddr)
{
    asm volatile("ldmatrix.sync.aligned.m8n8.x4.shared.b16 {%0,%1,%2,%3}, [%4];"
        : "=r"(r[0]), "=r"(r[1]), "=r"(r[2]), "=r"(r[3]) : "r"(saddr));
}

__device__ __forceinline__ void ldsm_x4_t(uint32_t* r, uint32_t saddr)
{
    asm volatile("ldmatrix.sync.aligned.m8n8.x4.trans.shared.b16 {%0,%1,%2,%3}, [%4];"
        : "=r"(r[0]), "=r"(r[1]), "=r"(r[2]), "=r"(r[3]) : "r"(saddr));
}

__device__ __forceinline__ void cp_async16(uint32_t saddr, const void* gptr)
{
    asm volatile("cp.async.cg.shared.global [%0], [%1], 16;"
        :: "r"(saddr), "l"(gptr));
}
#define CP_COMMIT() asm volatile("cp.async.commit_group;" ::: "memory")
#define CP_WAIT0()  asm volatile("cp.async.wait_group 0;" ::: "memory")

__device__ __forceinline__ void cvt_pair(float x, float y, uint32_t& hi, uint32_t& mid)
{
    __nv_bfloat162 h = __floats2bfloat162_rn(x, y);
    float rx = x - __bfloat162float(__low2bfloat16(h));
    float ry = y - __bfloat162float(__high2bfloat16(h));
    __nv_bfloat162 m = __floats2bfloat162_rn(rx, ry);
    hi  = *reinterpret_cast<uint32_t*>(&h);
    mid = *reinterpret_cast<uint32_t*>(&m);
}

// ---------------------------------------------------------------------------
// Fused prep: split x/wqkv/wproj into hi/mid planes + zero rowsums. One launch.
// ---------------------------------------------------------------------------
#define N4_X   (MTOK * CDIM / 4)
#define N4_WQ  (QKVC * CDIM / 4)
#define N4_WP  (CDIM * CDIM / 4)
#define N4_RS  (BATCH * HEADS * SEQ / 4)

__global__ __launch_bounds__(256) void prep_kernel(
    const float* __restrict__ x, const float* __restrict__ wq,
    const float* __restrict__ wp,
    __nv_bfloat16* __restrict__ x_hi, __nv_bfloat16* __restrict__ x_mid,
    __nv_bfloat16* __restrict__ wq_hi, __nv_bfloat16* __restrict__ wq_mid,
    __nv_bfloat16* __restrict__ wp_hi, __nv_bfloat16* __restrict__ wp_mid,
    float* __restrict__ rs)
{
    int i = blockIdx.x * blockDim.x + threadIdx.x;
    const float* src; __nv_bfloat16 *hi, *mid; int off;
    if (i < N4_X)                        { src = x;  hi = x_hi;  mid = x_mid;  off = 0; }
    else if (i < N4_X + N4_WQ)           { src = wq; hi = wq_hi; mid = wq_mid; off = N4_X; }
    else if (i < N4_X + N4_WQ + N4_WP)   { src = wp; hi = wp_hi; mid = wp_mid; off = N4_X + N4_WQ; }
    else if (i < N4_X + N4_WQ + N4_WP + N4_RS) {
        ((float4*)rs)[i - (N4_X + N4_WQ + N4_WP)] = make_float4(0.f, 0.f, 0.f, 0.f);
        return;
    } else return;
    int j = i - off;
    float4 v = ((const float4*)src)[j];
    uint32_t h0, m0, h1, m1;
    cvt_pair(v.x, v.y, h0, m0);
    cvt_pair(v.z, v.w, h1, m1);
    ((uint2*)hi)[j]  = make_uint2(h0, h1);
    ((uint2*)mid)[j] = make_uint2(m0, m1);
}

// ---------------------------------------------------------------------------
// Batched GEMM on pre-split bf16 hi/mid operands. 3 MMAs (hh, hm, mh).
// ASRC=0: A via cp.async from (Ahi,Amid).
// ASRC=1: A from Af32: normalize by 1/rowsum, write back normalized P
//         in place (attn output), split to hi/mid in smem (PV kernel).
// BTRANS=0: B [N,K] k-contig (ldmatrix). BTRANS=1: B [K,N] n-contig (ldmatrix.trans).
// OUT=0: C fp32 + bias.  OUT=1: exp(alpha*acc) fp32 + rowsum atomics.
// OUT=2: C -> hi/mid planes.
// MINB: min blocks per SM for launch_bounds (occupancy control).
// ---------------------------------------------------------------------------
template<int BM, int BN, int WM, int WN, int ASRC, int BTRANS, int OUT, int MINB = 2>
__global__ __launch_bounds__(256, MINB) void gemm3(
    const __nv_bfloat16* __restrict__ Ahi, const __nv_bfloat16* __restrict__ Amid,
    float* __restrict__ Af32, int lda, long long sa1, long long sa2,
    const __nv_bfloat16* __restrict__ Bhi, const __nv_bfloat16* __restrict__ Bmid,
    int ldb, long long sb1, long long sb2,
    float* __restrict__ Cf, __nv_bfloat16* __restrict__ Chi, __nv_bfloat16* __restrict__ Cmid,
    int ldc, long long sc1, long long sc2,
    int K, int nz2, float alpha, const float* __restrict__ bias,
    float* __restrict__ rowsum)
{
    constexpr int BK  = 32;
    constexpr int BKP = 40;       // A / B(k-contig) row stride, 80B = 16B-aligned
    constexpr int BNP = 72;       // B(trans) row stride, 144B = 16B-aligned
    constexpr int MW  = BM / WM;
    constexpr int MF  = WM / 16;
    constexpr int NF  = WN / 8;
    constexpr int A_TPR = 256 / BM;        // threads per A row (2 for BM=128, 4 for BM=64)
    constexpr int A_EPT = BK / A_TPR;      // elems per thread (16 or 8)

    extern __shared__ __nv_bfloat16 sm[];
    __nv_bfloat16* Asm = sm;                         // [2][2][BM][BKP]
    __nv_bfloat16* Bsm = sm + 4 * BM * BKP;
#define ASM(bb,s,m,k)  Asm[(((bb)*2+(s))*BM + (m))*BKP + (k)]
#define BSM(bb,s,n,k)  Bsm[(((bb)*2+(s))*BN + (n))*BKP + (k)]
#define BSMT(bb,s,k,n) Bsm[(((bb)*2+(s))*BK + (k))*BNP + (n)]
    const uint32_t asm_u32 = (uint32_t)__cvta_generic_to_shared(Asm);
    const uint32_t bsm_u32 = (uint32_t)__cvta_generic_to_shared(Bsm);

    const int z  = blockIdx.z;
    const int z1 = z / nz2, z2 = z - z1 * nz2;
    const long long zofA = z1 * sa1 + z2 * sa2;
    const long long zofB = z1 * sb1 + z2 * sb2;
    const long long zofC = z1 * sc1 + z2 * sc2;

    const int m0  = blockIdx.y * BM;
    const int n0  = blockIdx.x * BN;
    const int tid = threadIdx.x;
    const int w    = tid >> 5, lane = tid & 31;
    const int wm   = w % MW,   wn   = w / MW;
    const int g    = lane >> 2;
    const int t2   = (lane & 3) * 2;

    // ldmatrix lane offsets (proven mappings — do not touch)
    const int a_row_off = ((lane >> 3) & 1) * 8 + (lane & 7);
    const int a_col_off = (lane >> 4) * 8;
    const int b_row_off = (lane >> 4) * 8 + (lane & 7);
    const int b_col_off = ((lane >> 3) & 1) * 8;
    const int bt_k_off = ((lane >> 3) & 1) * 8 + (lane & 7);
    const int bt_n_off = (lane >> 4) * 8;

    float acc[MF][NF][4];
#pragma unroll
    for (int i = 0; i < MF; i++)
#pragma unroll
        for (int j = 0; j < NF; j++)
#pragma unroll
            for (int q = 0; q < 4; q++) acc[i][j][q] = 0.0f;

    // ---- staging indices ----
    const int a_row = tid / A_TPR;                   // 0..BM-1
    const int a_seg = (tid % A_TPR) * A_EPT;
    const int bt_k  = tid >> 3;                      // 0..31
    const int bt_sg = (tid & 7) * 8;

    float anorm = 1.0f;
    if (ASRC == 1)
        anorm = 1.0f / rowsum[(size_t)z * SEQ + m0 + a_row];

    // issue all copies for k-tile kt into buffer bb
    auto issue_tile = [&](int kt, int bb) {
        if (ASRC == 0) {
            const __nv_bfloat16* ph = Ahi + zofA + (size_t)(m0 + a_row) * lda + kt + a_seg;
            const __nv_bfloat16* pm = Amid + zofA + (size_t)(m0 + a_row) * lda + kt + a_seg;
            uint32_t d0 = asm_u32 + (uint32_t)((((bb * 2 + 0) * BM + a_row) * BKP + a_seg) * 2);
            uint32_t d1 = asm_u32 + (uint32_t)((((bb * 2 + 1) * BM + a_row) * BKP + a_seg) * 2);
#pragma unroll
            for (int e = 0; e < A_EPT; e += 8) {
                cp_async16(d0 + 2 * e, ph + e);
                cp_async16(d1 + 2 * e, pm + e);
            }
        } else {
            float* Ap = Af32 + zofA + (size_t)(m0 + a_row) * lda + kt + a_seg;
            float4 raf[A_EPT / 4];
#pragma unroll
            for (int q = 0; q < A_EPT / 4; q++) {
                raf[q] = *(const float4*)(Ap + 4 * q);
                raf[q].x *= anorm; raf[q].y *= anorm;
                raf[q].z *= anorm; raf[q].w *= anorm;
                *(float4*)(Ap + 4 * q) = raf[q];   // write back normalized P (attn output)
            }
#pragma unroll
            for (int q = 0; q < A_EPT / 4; q++) {
                uint32_t hi, mid;
                cvt_pair(raf[q].x, raf[q].y, hi, mid);
                *(uint32_t*)&ASM(bb, 0, a_row, a_seg + 4 * q)     = hi;
                *(uint32_t*)&ASM(bb, 1, a_row, a_seg + 4 * q)     = mid;
                cvt_pair(raf[q].z, raf[q].w, hi, mid);
                *(uint32_t*)&ASM(bb, 0, a_row, a_seg + 4 * q + 2) = hi;
                *(uint32_t*)&ASM(bb, 1, a_row, a_seg + 4 * q + 2) = mid;
            }
        }
        if (BTRANS == 0) {
            // B staging uses 2 threads/row over BN=128 rows (requires BN=128)
            const int b_row = tid >> 1;
            const int b_seg = (tid & 1) * 16;
            const __nv_bfloat16* ph = Bhi + zofB + (size_t)(n0 + b_row) * ldb + kt + b_seg;
            const __nv_bfloat16* pm = Bmid + zofB + (size_t)(n0 + b_row) * ldb + kt + b_seg;
            uint32_t d0 = bsm_u32 + (uint32_t)((((bb * 2 + 0) * BN + b_row) * BKP + b_seg) * 2);
            uint32_t d1 = bsm_u32 + (uint32_t)((((bb * 2 + 1) * BN + b_row) * BKP + b_seg) * 2);
            cp_async16(d0,      ph);
            cp_async16(d0 + 16, ph + 8);
            cp_async16(d1,      pm);
            cp_async16(d1 + 16, pm + 8);
        } else {
            const __nv_bfloat16* ph = Bhi + zofB + (size_t)(kt + bt_k) * ldb + n0 + bt_sg;
            const __nv_bfloat16* pm = Bmid + zofB + (size_t)(kt + bt_k) * ldb + n0 + bt_sg;
            uint32_t d0 = bsm_u32 + (uint32_t)((((bb * 2 + 0) * BK + bt_k) * BNP + bt_sg) * 2);
            uint32_t d1 = bsm_u32 + (uint32_t)((((bb * 2 + 1) * BK + bt_k) * BNP + bt_sg) * 2);
            cp_async16(d0, ph);
            cp_async16(d1, pm);
        }
    };

    const int iters = K / BK;

    issue_tile(0, 0);
    CP_COMMIT();
    CP_WAIT0();
    __syncthreads();

    for (int it = 0; it < iters; it++) {
        const int buf = it & 1;
        const bool more = (it + 1 < iters);
        if (more) {
            issue_tile((it + 1) * BK, buf ^ 1);   // overlaps with compute below
            CP_COMMIT();
        }

#pragma unroll
        for (int ks = 0; ks < BK; ks += 16) {
            uint32_t af[2][MF][4], bf[2][NF][2];
#pragma unroll
            for (int s = 0; s < 2; s++) {
#pragma unroll
                for (int i = 0; i < MF; i++) {
                    int row = wm * WM + i * 16 + a_row_off;
                    int col = ks + a_col_off;
                    uint32_t addr = asm_u32 +
                        (uint32_t)((((buf * 2 + s) * BM + row) * BKP + col) * 2);
                    ldsm_x4(af[s][i], addr);
                }
#pragma unroll
                for (int jj = 0; jj < NF / 2; jj++) {
                    uint32_t r[4];
                    if (BTRANS == 0) {
                        int row = wn * WN + jj * 16 + b_row_off;
                        int col = ks + b_col_off;
                        uint32_t addr = bsm_u32 +
                            (uint32_t)((((buf * 2 + s) * BN + row) * BKP + col) * 2);
                        ldsm_x4(r, addr);
                    } else {
                        int kR = ks + bt_k_off;
                        int nB = wn * WN + jj * 16 + bt_n_off;
                        uint32_t addr = bsm_u32 +
                            (uint32_t)((((buf * 2 + s) * BK + kR) * BNP + nB) * 2);
                        ldsm_x4_t(r, addr);
                    }
                    bf[s][jj * 2 + 0][0] = r[0]; bf[s][jj * 2 + 0][1] = r[1];
                    bf[s][jj * 2 + 1][0] = r[2]; bf[s][jj * 2 + 1][1] = r[3];
                }
            }
#pragma unroll
            for (int i = 0; i < MF; i++)
#pragma unroll
                for (int j = 0; j < NF; j++) {
                    mma16816(acc[i][j], af[0][i], bf[0][j]);   // hi*hi
                    mma16816(acc[i][j], af[0][i], bf[1][j]);   // hi*mid
                    mma16816(acc[i][j], af[1][i], bf[0][j]);   // mid*hi
                }
        }

        if (more) CP_WAIT0();
        __syncthreads();
    }

    // ---- epilogue ----
    if (OUT == 1) {
        float* C = Cf + zofC;
        float rs[MF][2];
#pragma unroll
        for (int i = 0; i < MF; i++) { rs[i][0] = 0.0f; rs[i][1] = 0.0f; }
#pragma unroll
        for (int i = 0; i < MF; i++) {
            int r = m0 + wm * WM + i * 16 + g;
#pragma unroll
            for (int j = 0; j < NF; j++) {
                int c = n0 + wn * WN + j * 8 + t2;
                float e0 = __expf(alpha * acc[i][j][0]);
                float e1 = __expf(alpha * acc[i][j][1]);
                float e2 = __expf(alpha * acc[i][j][2]);
                float e3 = __expf(alpha * acc[i][j][3]);
                *(float2*)&C[(size_t)r * ldc + c]       = make_float2(e0, e1);
                *(float2*)&C[(size_t)(r + 8) * ldc + c] = make_float2(e2, e3);
                rs[i][0] += e0 + e1;
                rs[i][1] += e2 + e3;
            }
        }
#pragma unroll
        for (int i = 0; i < MF; i++) {
            rs[i][0] += __shfl_xor_sync(0xffffffffu, rs[i][0], 1);
            rs[i][0] += __shfl_xor_sync(0xffffffffu, rs[i][0], 2);
            rs[i][1] += __shfl_xor_sync(0xffffffffu, rs[i][1], 1);
            rs[i][1] += __shfl_xor_sync(0xffffffffu, rs[i][1], 2);
        }
        if ((lane & 3) == 0) {
            size_t base = (size_t)z * SEQ + m0 + wm * WM;
#pragma unroll
            for (int i = 0; i < MF; i++) {
                atomicAdd(&rowsum[base + i * 16 + g],     rs[i][0]);
                atomicAdd(&rowsum[base + i * 16 + 8 + g], rs[i][1]);
            }
        }
    } else if (OUT == 2) {
        __nv_bfloat16* Ch = Chi + zofC;
        __nv_bfloat16* Cm = Cmid + zofC;
#pragma unroll
        for (int i = 0; i < MF; i++) {
            int r = m0 + wm * WM + i * 16 + g;
#pragma unroll
            for (int j = 0; j < NF; j++) {
                int c = n0 + wn * WN + j * 8 + t2;
                uint32_t h, mm;
                cvt_pair(acc[i][j][0], acc[i][j][1], h, mm);
                *(uint32_t*)&Ch[(size_t)r * ldc + c] = h;
                *(uint32_t*)&Cm[(size_t)r * ldc + c] = mm;
                cvt_pair(acc[i][j][2], acc[i][j][3], h, mm);
                *(uint32_t*)&Ch[(size_t)(r + 8) * ldc + c] = h;
                *(uint32_t*)&Cm[(size_t)(r + 8) * ldc + c] = mm;
            }
        }
    } else {
        float* C = Cf + zofC;
#pragma unroll
        for (int i = 0; i < MF; i++) {
            int r = m0 + wm * WM + i * 16 + g;
#pragma unroll
            for (int j = 0; j < NF; j++) {
                int c = n0 + wn * WN + j * 8 + t2;
                float b0 = bias ? bias[c]     : 0.0f;
                float b1 = bias ? bias[c + 1] : 0.0f;
                *(float2*)&C[(size_t)r * ldc + c] =
                    make_float2(acc[i][j][0] + b0, acc[i][j][1] + b1);
                *(float2*)&C[(size_t)(r + 8) * ldc + c] =
                    make_float2(acc[i][j][2] + b0, acc[i][j][3] + b1);
            }
        }
    }
#undef ASM
#undef BSM
#undef BSMT
}

// ---------------------------------------------------------------------------
extern "C" void kernel_launch(void* const* d_in, const int* in_sizes, int n_in,
                              void* d_out, int out_size)
{
    const float* x      = (const float*)d_in[0];   // [8,1024,768]
    const float* qkv_w  = (const float*)d_in[1];   // [2304,768]
    const float* proj_w = (const float*)d_in[2];   // [768,768]
    const float* proj_b = (const float*)d_in[3];   // [768]

    float* out_proj = (float*)d_out;                          // [8,1024,768]
    float* out_attn = (float*)d_out + (size_t)MTOK * CDIM;    // [8,12,1024,1024]

    __nv_bfloat16 *x_hi, *x_mid, *wq_hi, *wq_mid, *wp_hi, *wp_mid;
    __nv_bfloat16 *qkv_hi, *qkv_mid, *ctx_hi, *ctx_mid;
    float* rsum;
    cudaGetSymbolAddress((void**)&x_hi,   g_x_hi);
    cudaGetSymbolAddress((void**)&x_mid,  g_x_mid);
    cudaGetSymbolAddress((void**)&wq_hi,  g_wqkv_hi);
    cudaGetSymbolAddress((void**)&wq_mid, g_wqkv_mid);
    cudaGetSymbolAddress((void**)&wp_hi,  g_wproj_hi);
    cudaGetSymbolAddress((void**)&wp_mid, g_wproj_mid);
    cudaGetSymbolAddress((void**)&qkv_hi, g_qkv_hi);
    cudaGetSymbolAddress((void**)&qkv_mid,g_qkv_mid);
    cudaGetSymbolAddress((void**)&ctx_hi, g_ctx_hi);
    cudaGetSymbolAddress((void**)&ctx_mid,g_ctx_mid);
    cudaGetSymbolAddress((void**)&rsum,   g_rowsum);

    constexpr int BKP = 40, BNP = 72;
    constexpr int SM_KC = (4 * 128 * BKP + 4 * 128 * BKP) * 2;   // 81920 B
    constexpr int SM_PV = (4 * 64 * BKP + 4 * 32 * BNP) * 2;     // 38912 B

    cudaFuncSetAttribute((const void*)gemm3<128,128,64,32,0,0,2>,
                         cudaFuncAttributeMaxDynamicSharedMemorySize, SM_KC);
    cudaFuncSetAttribute((const void*)gemm3<128,128,64,32,0,0,1>,
                         cudaFuncAttributeMaxDynamicSharedMemorySize, SM_KC);
    cudaFuncSetAttribute((const void*)gemm3<64,64,32,16,1,1,2,3>,
                         cudaFuncAttributeMaxDynamicSharedMemorySize, SM_PV);
    cudaFuncSetAttribute((const void*)gemm3<128,128,64,32,0,0,0>,
                         cudaFuncAttributeMaxDynamicSharedMemorySize, SM_KC);

    // 0) fused prep: splits + rowsum zero (one launch)
    {
        int total = N4_X + N4_WQ + N4_WP + N4_RS;
        prep_kernel<<<(total + 255) / 256, 256>>>(
            x, qkv_w, proj_w, x_hi, x_mid, wq_hi, wq_mid, wp_hi, wp_mid, rsum);
    }

    // 1) QKV GEMM -> split planes g_qkv
    gemm3<128,128,64,32,0,0,2><<<dim3(QKVC/128, MTOK/128, 1), 256, SM_KC>>>(
        x_hi, x_mid, nullptr, CDIM, 0, 0,
        wq_hi, wq_mid, CDIM, 0, 0,
        nullptr, qkv_hi, qkv_mid, QKVC, 0, 0,
        CDIM, 1, 1.0f, nullptr, rsum);

    // 2) E = exp(0.125 * Q @ K^T) -> out_attn (fp32), rowsums
    gemm3<128,128,64,32,0,0,1><<<dim3(SEQ/128, SEQ/128, BATCH*HEADS), 256, SM_KC>>>(
        qkv_hi, qkv_mid, nullptr, QKVC, (long long)SEQ * QKVC, 64,
        qkv_hi + CDIM, qkv_mid + CDIM, QKVC, (long long)SEQ * QKVC, 64,
        out_attn, nullptr, nullptr, SEQ,
        (long long)HEADS * SEQ * SEQ, (long long)SEQ * SEQ,
        64, HEADS, 0.125f, nullptr, rsum);

    // 3) ctx = P @ V; normalizes E->P in place (attn output). 64x64 tiles,
    //    3 CTAs/SM for latency hiding (PV was latency-bound at occ 22%).
    gemm3<64,64,32,16,1,1,2,3><<<dim3(1, SEQ/64, BATCH*HEADS), 256, SM_PV>>>(
        nullptr, nullptr, out_attn, SEQ,
        (long long)HEADS * SEQ * SEQ, (long long)SEQ * SEQ,
        qkv_hi + 2 * CDIM, qkv_mid + 2 * CDIM, QKVC, (long long)SEQ * QKVC, 64,
        nullptr, ctx_hi, ctx_mid, CDIM, (long long)SEQ * CDIM, 64,
        SEQ, HEADS, 1.0f, nullptr, rsum);

    // 4) proj: ctx @ proj_w^T + bias -> out (fp32)
    gemm3<128,128,64,32,0,0,0><<<dim3(CDIM/128, MTOK/128, 1), 256, SM_KC>>>(
        ctx_hi, ctx_mid, nullptr, CDIM, 0, 0,
        wp_hi, wp_mid, CDIM, 0, 0,
        out_proj, nullptr, nullptr, CDIM, 0, 0,
        CDIM, 1, 1.0f, proj_b, rsum);
}

// round 12
// speedup vs baseline: 1.1703x; 1.0568x over previous
#include <cuda_runtime.h>
#include <cuda_bf16.h>
#include <cstdint>
#include <cstddef>

#define BATCH 8
#define SEQ   1024
#define CDIM  768
#define HEADS 12
#define MTOK  (BATCH*SEQ)      // 8192
#define QKVC  (3*CDIM)         // 2304
#define DHEAD 64

// Persistent scratch (device globals — allocation is forbidden)
__device__ __nv_bfloat16 g_x_hi   [(size_t)MTOK * CDIM];
__device__ __nv_bfloat16 g_x_mid  [(size_t)MTOK * CDIM];
__device__ __nv_bfloat16 g_wqkv_hi [(size_t)QKVC * CDIM];
__device__ __nv_bfloat16 g_wqkv_mid[(size_t)QKVC * CDIM];
__device__ __nv_bfloat16 g_wproj_hi [(size_t)CDIM * CDIM];
__device__ __nv_bfloat16 g_wproj_mid[(size_t)CDIM * CDIM];
__device__ __nv_bfloat16 g_qkv_hi [(size_t)MTOK * QKVC];
__device__ __nv_bfloat16 g_qkv_mid[(size_t)MTOK * QKVC];
__device__ __nv_bfloat16 g_ctx_hi [(size_t)MTOK * CDIM];
__device__ __nv_bfloat16 g_ctx_mid[(size_t)MTOK * CDIM];

// ---------------------------------------------------------------------------
__device__ __forceinline__ void mma16816(float* d, const uint32_t* a, const uint32_t* b)
{
    asm volatile(
        "mma.sync.aligned.m16n8k16.row.col.f32.bf16.bf16.f32 "
        "{%0,%1,%2,%3},{%4,%5,%6,%7},{%8,%9},{%0,%1,%2,%3};\n"
        : "+f"(d[0]), "+f"(d[1]), "+f"(d[2]), "+f"(d[3])
        : "r"(a[0]), "r"(a[1]), "r"(a[2]), "r"(a[3]), "r"(b[0]), "r"(b[1]));
}

__device__ __forceinline__ void ldsm_x4(uint32_t* r, uint32_t saddr)
{
    asm volatile("ldmatrix.sync.aligned.m8n8.x4.shared.b16 {%0,%1,%2,%3}, [%4];"
        : "=r"(r[0]), "=r"(r[1]), "=r"(r[2]), "=r"(r[3]) : "r"(saddr));
}

__device__ __forceinline__ void ldsm_x4_t(uint32_t* r, uint32_t saddr)
{
    asm volatile("ldmatrix.sync.aligned.m8n8.x4.trans.shared.b16 {%0,%1,%2,%3}, [%4];"
        : "=r"(r[0]), "=r"(r[1]), "=r"(r[2]), "=r"(r[3]) : "r"(saddr));
}

__device__ __forceinline__ void cp_async16(uint32_t saddr, const void* gptr)
{
    asm volatile("cp.async.cg.shared.global [%0], [%1], 16;"
        :: "r"(saddr), "l"(gptr));
}
#define CP_COMMIT() asm volatile("cp.async.commit_group;" ::: "memory")
#define CP_WAIT0()  asm volatile("cp.async.wait_group 0;" ::: "memory")

__device__ __forceinline__ void cvt_pair(float x, float y, uint32_t& hi, uint32_t& mid)
{
    __nv_bfloat162 h = __floats2bfloat162_rn(x, y);
    float rx = x - __bfloat162float(__low2bfloat16(h));
    float ry = y - __bfloat162float(__high2bfloat16(h));
    __nv_bfloat162 m = __floats2bfloat162_rn(rx, ry);
    hi  = *reinterpret_cast<uint32_t*>(&h);
    mid = *reinterpret_cast<uint32_t*>(&m);
}

// ---------------------------------------------------------------------------
// Fused prep: split x/wqkv/wproj into hi/mid planes. One launch.
// ---------------------------------------------------------------------------
#define N4_X   (MTOK * CDIM / 4)
#define N4_WQ  (QKVC * CDIM / 4)
#define N4_WP  (CDIM * CDIM / 4)

__global__ __launch_bounds__(256) void prep_kernel(
    const float* __restrict__ x, const float* __restrict__ wq,
    const float* __restrict__ wp,
    __nv_bfloat16* __restrict__ x_hi, __nv_bfloat16* __restrict__ x_mid,
    __nv_bfloat16* __restrict__ wq_hi, __nv_bfloat16* __restrict__ wq_mid,
    __nv_bfloat16* __restrict__ wp_hi, __nv_bfloat16* __restrict__ wp_mid)
{
    int i = blockIdx.x * blockDim.x + threadIdx.x;
    const float* src; __nv_bfloat16 *hi, *mid; int off;
    if (i < N4_X)                        { src = x;  hi = x_hi;  mid = x_mid;  off = 0; }
    else if (i < N4_X + N4_WQ)           { src = wq; hi = wq_hi; mid = wq_mid; off = N4_X; }
    else if (i < N4_X + N4_WQ + N4_WP)   { src = wp; hi = wp_hi; mid = wp_mid; off = N4_X + N4_WQ; }
    else return;
    int j = i - off;
    float4 v = ((const float4*)src)[j];
    uint32_t h0, m0, h1, m1;
    cvt_pair(v.x, v.y, h0, m0);
    cvt_pair(v.z, v.w, h1, m1);
    ((uint2*)hi)[j]  = make_uint2(h0, h1);
    ((uint2*)mid)[j] = make_uint2(m0, m1);
}

// ---------------------------------------------------------------------------
// GEMM on pre-split bf16 hi/mid operands (QKV + proj). Proven R8 path.
// ---------------------------------------------------------------------------
template<int OUT>   // 0: fp32+bias, 2: hi/mid planes
__global__ __launch_bounds__(256, 2) void gemm3(
    const __nv_bfloat16* __restrict__ Ahi, const __nv_bfloat16* __restrict__ Amid, int lda,
    const __nv_bfloat16* __restrict__ Bhi, const __nv_bfloat16* __restrict__ Bmid, int ldb,
    float* __restrict__ Cf, __nv_bfloat16* __restrict__ Chi, __nv_bfloat16* __restrict__ Cmid,
    int ldc, int K, const float* __restrict__ bias)
{
    constexpr int BM = 128, BN = 128, WM = 64, WN = 32;
    constexpr int BK = 32, BKP = 40;
    constexpr int MW = BM / WM, MF = WM / 16, NF = WN / 8;

    extern __shared__ __nv_bfloat16 sm[];
    __nv_bfloat16* Asm = sm;
    __nv_bfloat16* Bsm = sm + 4 * BM * BKP;
#define ASM(bb,s,m,k)  Asm[(((bb)*2+(s))*BM + (m))*BKP + (k)]
#define BSM(bb,s,n,k)  Bsm[(((bb)*2+(s))*BN + (n))*BKP + (k)]
    const uint32_t asm_u32 = (uint32_t)__cvta_generic_to_shared(Asm);
    const uint32_t bsm_u32 = (uint32_t)__cvta_generic_to_shared(Bsm);

    const int m0 = blockIdx.y * BM, n0 = blockIdx.x * BN;
    const int tid = threadIdx.x, w = tid >> 5, lane = tid & 31;
    const int wm = w % MW, wn = w / MW;
    const int g = lane >> 2, t2 = (lane & 3) * 2;

    const int a_row_off = ((lane >> 3) & 1) * 8 + (lane & 7);
    const int a_col_off = (lane >> 4) * 8;
    const int b_row_off = (lane >> 4) * 8 + (lane & 7);
    const int b_col_off = ((lane >> 3) & 1) * 8;

    float acc[MF][NF][4];
#pragma unroll
    for (int i = 0; i < MF; i++)
#pragma unroll
        for (int j = 0; j < NF; j++)
#pragma unroll
            for (int q = 0; q < 4; q++) acc[i][j][q] = 0.0f;

    const int a_row = tid >> 1, a_seg = (tid & 1) * 16;

    auto issue_tile = [&](int kt, int bb) {
        const __nv_bfloat16* ph = Ahi + (size_t)(m0 + a_row) * lda + kt + a_seg;
        const __nv_bfloat16* pm = Amid + (size_t)(m0 + a_row) * lda + kt + a_seg;
        uint32_t d0 = asm_u32 + (uint32_t)((((bb * 2 + 0) * BM + a_row) * BKP + a_seg) * 2);
        uint32_t d1 = asm_u32 + (uint32_t)((((bb * 2 + 1) * BM + a_row) * BKP + a_seg) * 2);
        cp_async16(d0, ph);      cp_async16(d0 + 16, ph + 8);
        cp_async16(d1, pm);      cp_async16(d1 + 16, pm + 8);
        const __nv_bfloat16* qh = Bhi + (size_t)(n0 + a_row) * ldb + kt + a_seg;
        const __nv_bfloat16* qm = Bmid + (size_t)(n0 + a_row) * ldb + kt + a_seg;
        uint32_t e0 = bsm_u32 + (uint32_t)((((bb * 2 + 0) * BN + a_row) * BKP + a_seg) * 2);
        uint32_t e1 = bsm_u32 + (uint32_t)((((bb * 2 + 1) * BN + a_row) * BKP + a_seg) * 2);
        cp_async16(e0, qh);      cp_async16(e0 + 16, qh + 8);
        cp_async16(e1, qm);      cp_async16(e1 + 16, qm + 8);
    };

    const int iters = K / BK;
    issue_tile(0, 0);
    CP_COMMIT(); CP_WAIT0(); __syncthreads();

    for (int it = 0; it < iters; it++) {
        const int buf = it & 1;
        const bool more = (it + 1 < iters);
        if (more) { issue_tile((it + 1) * BK, buf ^ 1); CP_COMMIT(); }

#pragma unroll
        for (int ks = 0; ks < BK; ks += 16) {
            uint32_t af[2][MF][4], bf[2][NF][2];
#pragma unroll
            for (int s = 0; s < 2; s++) {
#pragma unroll
                for (int i = 0; i < MF; i++) {
                    int row = wm * WM + i * 16 + a_row_off;
                    uint32_t addr = asm_u32 +
                        (uint32_t)((((buf * 2 + s) * BM + row) * BKP + ks + a_col_off) * 2);
                    ldsm_x4(af[s][i], addr);
                }
#pragma unroll
                for (int jj = 0; jj < NF / 2; jj++) {
                    int row = wn * WN + jj * 16 + b_row_off;
                    uint32_t addr = bsm_u32 +
                        (uint32_t)((((buf * 2 + s) * BN + row) * BKP + ks + b_col_off) * 2);
                    uint32_t r[4];
                    ldsm_x4(r, addr);
                    bf[s][jj * 2 + 0][0] = r[0]; bf[s][jj * 2 + 0][1] = r[1];
                    bf[s][jj * 2 + 1][0] = r[2]; bf[s][jj * 2 + 1][1] = r[3];
                }
            }
#pragma unroll
            for (int i = 0; i < MF; i++)
#pragma unroll
                for (int j = 0; j < NF; j++) {
                    mma16816(acc[i][j], af[0][i], bf[0][j]);
                    mma16816(acc[i][j], af[0][i], bf[1][j]);
                    mma16816(acc[i][j], af[1][i], bf[0][j]);
                }
        }
        if (more) CP_WAIT0();
        __syncthreads();
    }

#pragma unroll
    for (int i = 0; i < MF; i++) {
        int r = m0 + wm * WM + i * 16 + g;
#pragma unroll
        for (int j = 0; j < NF; j++) {
            int c = n0 + wn * WN + j * 8 + t2;
            if (OUT == 2) {
                uint32_t h, mm;
                cvt_pair(acc[i][j][0], acc[i][j][1], h, mm);
                *(uint32_t*)&Chi[(size_t)r * ldc + c] = h;
                *(uint32_t*)&Cmid[(size_t)r * ldc + c] = mm;
                cvt_pair(acc[i][j][2], acc[i][j][3], h, mm);
                *(uint32_t*)&Chi[(size_t)(r + 8) * ldc + c] = h;
                *(uint32_t*)&Cmid[(size_t)(r + 8) * ldc + c] = mm;
            } else {
                float b0 = bias ? bias[c] : 0.0f;
                float b1 = bias ? bias[c + 1] : 0.0f;
                *(float2*)&Cf[(size_t)r * ldc + c] =
                    make_float2(acc[i][j][0] + b0, acc[i][j][1] + b1);
                *(float2*)&Cf[(size_t)(r + 8) * ldc + c] =
                    make_float2(acc[i][j][2] + b0, acc[i][j][3] + b1);
            }
        }
    }
#undef ASM
#undef BSM
}

// ---------------------------------------------------------------------------
// Fused attention: per CTA = 128 query rows × one (b,h). Two phases:
//  P1: loop K/V tiles, S=Q·K^T (3-MMA), exp in regs, rowsum (CTA-local),
//      U += E·V (3-MMA, C-frag→A-frag register reuse).
//  ctx = U/rowsum -> hi/mid planes.
//  P2: recompute S per tile, write P = exp(S)·inv -> attn (only big stream).
// ---------------------------------------------------------------------------
#define BMQ 128
#define KT  64
#define NKT (SEQ/KT)
#define QP  72

__global__ __launch_bounds__(256, 2) void fused_attn(
    const __nv_bfloat16* __restrict__ qkv_hi,
    const __nv_bfloat16* __restrict__ qkv_mid,
    float* __restrict__ attn,
    __nv_bfloat16* __restrict__ ctx_hi,
    __nv_bfloat16* __restrict__ ctx_mid)
{
    extern __shared__ __nv_bfloat16 sm[];
    __nv_bfloat16* Qs = sm;                  // [2][128][72]
    __nv_bfloat16* Ks = Qs + 2 * BMQ * QP;   // [2][2][64][72]
    __nv_bfloat16* Vs = Ks + 4 * KT * QP;    // [2][2][64][72]
    const uint32_t qs_u = (uint32_t)__cvta_generic_to_shared(Qs);
    const uint32_t ks_u = (uint32_t)__cvta_generic_to_shared(Ks);
    const uint32_t vs_u = (uint32_t)__cvta_generic_to_shared(Vs);

    const int nb = blockIdx.x, h = blockIdx.y, b = blockIdx.z;
    const int tid = threadIdx.x, w = tid >> 5, lane = tid & 31;
    const int g = lane >> 2, t2 = (lane & 3) * 2;

    const size_t tokbase = (size_t)b * SEQ;
    const int qoff = h * DHEAD, koff = CDIM + h * DHEAD, voff = 2 * CDIM + h * DHEAD;

    const int a_row_off = ((lane >> 3) & 1) * 8 + (lane & 7);
    const int a_col_off = (lane >> 4) * 8;
    const int b_row_off = (lane >> 4) * 8 + (lane & 7);
    const int b_col_off = ((lane >> 3) & 1) * 8;
    const int bt_k_off  = ((lane >> 3) & 1) * 8 + (lane & 7);
    const int bt_n_off  = (lane >> 4) * 8;

    const int q_row = tid >> 1, q_seg = (tid & 1) * 32;    // Q staging
    const int kv_row = tid >> 2, kv_seg = (tid & 3) * 16;  // K/V staging

    // stage Q (once)
    {
        const __nv_bfloat16* qh = qkv_hi + (tokbase + nb * BMQ + q_row) * QKVC + qoff + q_seg;
        const __nv_bfloat16* qm = qkv_mid + (tokbase + nb * BMQ + q_row) * QKVC + qoff + q_seg;
        uint32_t d0 = qs_u + (uint32_t)(((0 * BMQ + q_row) * QP + q_seg) * 2);
        uint32_t d1 = qs_u + (uint32_t)(((1 * BMQ + q_row) * QP + q_seg) * 2);
#pragma unroll
        for (int e = 0; e < 32; e += 8) {
            cp_async16(d0 + 2 * e, qh + e);
            cp_async16(d1 + 2 * e, qm + e);
        }
    }

    auto issue_kv = [&](int kt2, int bb, bool withV) {
        const size_t tok = tokbase + kt2 * KT + kv_row;
        const __nv_bfloat16* kh = qkv_hi + tok * QKVC + koff + kv_seg;
        const __nv_bfloat16* km = qkv_mid + tok * QKVC + koff + kv_seg;
        uint32_t d0 = ks_u + (uint32_t)((((bb * 2 + 0) * KT + kv_row) * QP + kv_seg) * 2);
        uint32_t d1 = ks_u + (uint32_t)((((bb * 2 + 1) * KT + kv_row) * QP + kv_seg) * 2);
        cp_async16(d0, kh);      cp_async16(d0 + 16, kh + 8);
        cp_async16(d1, km);      cp_async16(d1 + 16, km + 8);
        if (withV) {
            const __nv_bfloat16* vh = qkv_hi + tok * QKVC + voff + kv_seg;
            const __nv_bfloat16* vm = qkv_mid + tok * QKVC + voff + kv_seg;
            uint32_t e0 = vs_u + (uint32_t)((((bb * 2 + 0) * KT + kv_row) * QP + kv_seg) * 2);
            uint32_t e1 = vs_u + (uint32_t)((((bb * 2 + 1) * KT + kv_row) * QP + kv_seg) * 2);
            cp_async16(e0, vh);      cp_async16(e0 + 16, vh + 8);
            cp_async16(e1, vm);      cp_async16(e1 + 16, vm + 8);
        }
    };

    float sacc[8][4];
    auto compute_S = [&](int buf) {
#pragma unroll
        for (int j = 0; j < 8; j++)
#pragma unroll
            for (int q = 0; q < 4; q++) sacc[j][q] = 0.0f;
#pragma unroll
        for (int ks = 0; ks < 4; ks++) {
            uint32_t af[2][4];
#pragma unroll
            for (int s = 0; s < 2; s++) {
                int row = w * 16 + a_row_off;
                ldsm_x4(af[s], qs_u +
                    (uint32_t)(((s * BMQ + row) * QP + ks * 16 + a_col_off) * 2));
            }
#pragma unroll
            for (int jj = 0; jj < 4; jj++) {
                uint32_t bh[4], bm[4];
                int row = jj * 16 + b_row_off;
                int col = ks * 16 + b_col_off;
                ldsm_x4(bh, ks_u + (uint32_t)((((buf * 2 + 0) * KT + row) * QP + col) * 2));
                ldsm_x4(bm, ks_u + (uint32_t)((((buf * 2 + 1) * KT + row) * QP + col) * 2));
                uint32_t b0h[2] = { bh[0], bh[1] }, b1h[2] = { bh[2], bh[3] };
                uint32_t b0m[2] = { bm[0], bm[1] }, b1m[2] = { bm[2], bm[3] };
                mma16816(sacc[jj * 2 + 0], af[0], b0h);
                mma16816(sacc[jj * 2 + 0], af[0], b0m);
                mma16816(sacc[jj * 2 + 0], af[1], b0h);
                mma16816(sacc[jj * 2 + 1], af[0], b1h);
                mma16816(sacc[jj * 2 + 1], af[0], b1m);
                mma16816(sacc[jj * 2 + 1], af[1], b1h);
            }
        }
    };

    float U[8][4];
#pragma unroll
    for (int j = 0; j < 8; j++)
#pragma unroll
        for (int q = 0; q < 4; q++) U[j][q] = 0.0f;
    float rs0 = 0.0f, rs1 = 0.0f;

    // ---------------- Phase 1 ----------------
    issue_kv(0, 0, true);
    CP_COMMIT(); CP_WAIT0(); __syncthreads();

    for (int kt = 0; kt < NKT; kt++) {
        const int buf = kt & 1;
        const bool more = (kt + 1 < NKT);
        if (more) { issue_kv(kt + 1, buf ^ 1, true); CP_COMMIT(); }

        compute_S(buf);

        // exp + rowsum
#pragma unroll
        for (int j = 0; j < 8; j++) {
            sacc[j][0] = __expf(0.125f * sacc[j][0]);
            sacc[j][1] = __expf(0.125f * sacc[j][1]);
            sacc[j][2] = __expf(0.125f * sacc[j][2]);
            sacc[j][3] = __expf(0.125f * sacc[j][3]);
            rs0 += sacc[j][0] + sacc[j][1];
            rs1 += sacc[j][2] + sacc[j][3];
        }

        // U += E @ V  (C-frag -> A-frag reuse)
#pragma unroll
        for (int ks = 0; ks < 4; ks++) {
            uint32_t ah[4], am[4];
            cvt_pair(sacc[2 * ks][0],     sacc[2 * ks][1],     ah[0], am[0]);
            cvt_pair(sacc[2 * ks][2],     sacc[2 * ks][3],     ah[1], am[1]);
            cvt_pair(sacc[2 * ks + 1][0], sacc[2 * ks + 1][1], ah[2], am[2]);
            cvt_pair(sacc[2 * ks + 1][2], sacc[2 * ks + 1][3], ah[3], am[3]);
#pragma unroll
            for (int jv = 0; jv < 4; jv++) {
                uint32_t rh[4], rm[4];
                int kR = ks * 16 + bt_k_off;
                int nB = jv * 16 + bt_n_off;
                ldsm_x4_t(rh, vs_u + (uint32_t)((((buf * 2 + 0) * KT + kR) * QP + nB) * 2));
                ldsm_x4_t(rm, vs_u + (uint32_t)((((buf * 2 + 1) * KT + kR) * QP + nB) * 2));
                uint32_t bh0[2] = { rh[0], rh[1] }, bh1[2] = { rh[2], rh[3] };
                uint32_t bm0[2] = { rm[0], rm[1] }, bm1[2] = { rm[2], rm[3] };
                mma16816(U[jv * 2 + 0], ah, bh0);
                mma16816(U[jv * 2 + 0], ah, bm0);
                mma16816(U[jv * 2 + 0], am, bh0);
                mma16816(U[jv * 2 + 1], ah, bh1);
                mma16816(U[jv * 2 + 1], ah, bm1);
                mma16816(U[jv * 2 + 1], am, bh1);
            }
        }

        if (more) CP_WAIT0();
        __syncthreads();
    }

    // rowsum reduce within quad (lanes sharing a row), all lanes get total
    rs0 += __shfl_xor_sync(0xffffffffu, rs0, 1);
    rs0 += __shfl_xor_sync(0xffffffffu, rs0, 2);
    rs1 += __shfl_xor_sync(0xffffffffu, rs1, 1);
    rs1 += __shfl_xor_sync(0xffffffffu, rs1, 2);
    const float inv0 = 1.0f / rs0;
    const float inv1 = 1.0f / rs1;

    // ctx = U * inv -> hi/mid planes
    {
        const size_t tok = tokbase + nb * BMQ + w * 16 + g;
        __nv_bfloat16* ch = ctx_hi + tok * CDIM + h * DHEAD;
        __nv_bfloat16* cm = ctx_mid + tok * CDIM + h * DHEAD;
#pragma unroll
        for (int jv = 0; jv < 8; jv++) {
            int c = jv * 8 + t2;
            uint32_t hh, mm;
            cvt_pair(U[jv][0] * inv0, U[jv][1] * inv0, hh, mm);
            *(uint32_t*)&ch[c] = hh;
            *(uint32_t*)&cm[c] = mm;
            cvt_pair(U[jv][2] * inv1, U[jv][3] * inv1, hh, mm);
            *(uint32_t*)&ch[8 * CDIM + c] = hh;
            *(uint32_t*)&cm[8 * CDIM + c] = mm;
        }
    }

    // ---------------- Phase 2: recompute S, write P ----------------
    issue_kv(0, 0, false);
    CP_COMMIT(); CP_WAIT0(); __syncthreads();

    float* dst0 = attn + ((size_t)(b * HEADS + h) * SEQ + nb * BMQ + w * 16 + g) * SEQ;
    float* dst1 = dst0 + 8 * SEQ;

    for (int kt = 0; kt < NKT; kt++) {
        const int buf = kt & 1;
        const bool more = (kt + 1 < NKT);
        if (more) { issue_kv(kt + 1, buf ^ 1, false); CP_COMMIT(); }

        compute_S(buf);

#pragma unroll
        for (int j = 0; j < 8; j++) {
            int c = kt * KT + j * 8 + t2;
            float e0 = __expf(0.125f * sacc[j][0]);
            float e1 = __expf(0.125f * sacc[j][1]);
            float e2 = __expf(0.125f * sacc[j][2]);
            float e3 = __expf(0.125f * sacc[j][3]);
            *(float2*)&dst0[c] = make_float2(e0 * inv0, e1 * inv0);
            *(float2*)&dst1[c] = make_float2(e2 * inv1, e3 * inv1);
        }

        if (more) CP_WAIT0();
        __syncthreads();
    }
}

// ---------------------------------------------------------------------------
extern "C" void kernel_launch(void* const* d_in, const int* in_sizes, int n_in,
                              void* d_out, int out_size)
{
    const float* x      = (const float*)d_in[0];
    const float* qkv_w  = (const float*)d_in[1];
    const float* proj_w = (const float*)d_in[2];
    const float* proj_b = (const float*)d_in[3];

    float* out_proj = (float*)d_out;
    float* out_attn = (float*)d_out + (size_t)MTOK * CDIM;

    __nv_bfloat16 *x_hi, *x_mid, *wq_hi, *wq_mid, *wp_hi, *wp_mid;
    __nv_bfloat16 *qkv_hi, *qkv_mid, *ctx_hi, *ctx_mid;
    cudaGetSymbolAddress((void**)&x_hi,   g_x_hi);
    cudaGetSymbolAddress((void**)&x_mid,  g_x_mid);
    cudaGetSymbolAddress((void**)&wq_hi,  g_wqkv_hi);
    cudaGetSymbolAddress((void**)&wq_mid, g_wqkv_mid);
    cudaGetSymbolAddress((void**)&wp_hi,  g_wproj_hi);
    cudaGetSymbolAddress((void**)&wp_mid, g_wproj_mid);
    cudaGetSymbolAddress((void**)&qkv_hi, g_qkv_hi);
    cudaGetSymbolAddress((void**)&qkv_mid,g_qkv_mid);
    cudaGetSymbolAddress((void**)&ctx_hi, g_ctx_hi);
    cudaGetSymbolAddress((void**)&ctx_mid,g_ctx_mid);

    constexpr int SM_KC = (4 * 128 * 40 + 4 * 128 * 40) * 2;                // 81920 B
    constexpr int SM_FA = (2 * BMQ * QP + 4 * KT * QP + 4 * KT * QP) * 2;   // 110592 B

    cudaFuncSetAttribute((const void*)gemm3<2>,
                         cudaFuncAttributeMaxDynamicSharedMemorySize, SM_KC);
    cudaFuncSetAttribute((const void*)gemm3<0>,
                         cudaFuncAttributeMaxDynamicSharedMemorySize, SM_KC);
    cudaFuncSetAttribute((const void*)fused_attn,
                         cudaFuncAttributeMaxDynamicSharedMemorySize, SM_FA);

    // 0) split inputs to hi/mid planes
    {
        int total = N4_X + N4_WQ + N4_WP;
        prep_kernel<<<(total + 255) / 256, 256>>>(
            x, qkv_w, proj_w, x_hi, x_mid, wq_hi, wq_mid, wp_hi, wp_mid);
    }

    // 1) QKV GEMM -> split planes
    gemm3<2><<<dim3(QKVC / 128, MTOK / 128), 256, SM_KC>>>(
        x_hi, x_mid, CDIM, wq_hi, wq_mid, CDIM,
        nullptr, qkv_hi, qkv_mid, QKVC, CDIM, nullptr);

    // 2) fused attention: S + softmax + attn write + PV
    fused_attn<<<dim3(SEQ / BMQ, HEADS, BATCH), 256, SM_FA>>>(
        qkv_hi, qkv_mid, out_attn, ctx_hi, ctx_mid);

    // 3) proj: ctx @ proj_w^T + bias -> out
    gemm3<0><<<dim3(CDIM / 128, MTOK / 128), 256, SM_KC>>>(
        ctx_hi, ctx_mid, CDIM, wp_hi, wp_mid, CDIM,
        out_proj, nullptr, nullptr, CDIM, CDIM, proj_b);
}